// round 1
// baseline (speedup 1.0000x reference)
#include <cuda_runtime.h>

#define S_LEN 2048
#define D_DIM 512
#define NH 8
#define DH 64
#define NROWS 4096   // B*S
#define NBH 16       // B*H

typedef unsigned long long u64t;

// ---------------- scratch (static device globals; no allocs) ----------------
__device__ float g_Q[NROWS * D_DIM];   // X @ Wq, row-major [4096][512]  (8 MB)
__device__ float g_g[D_DIM];           // g[h*64+j] = sum_k Wq[k, h*64+j] * Wv[k]
__device__ float g_v[NH * D_DIM];      // v[h][i] = sum_j Wq[i, h*64+j] * g[h*64+j]
__device__ float g_u[NBH * S_LEN];     // u[b,h,t] = X[b,t,:] . v[h]
__device__ float g_cn[NBH * S_LEN];    // -0.125*log2e*||Q_h[b,t]||

// ---------------- helpers ----------------
__device__ __forceinline__ void fma2(u64t& d, u64t a, u64t b) {
    asm("fma.rn.f32x2 %0, %1, %2, %0;" : "+l"(d) : "l"(a), "l"(b));
}
__device__ __forceinline__ u64t bcast2(float x) {
    u64t r; asm("mov.b64 %0, {%1, %1};" : "=l"(r) : "f"(x)); return r;
}
__device__ __forceinline__ float2 u2f(u64t v) {
    float2 r; asm("mov.b64 {%0, %1}, %2;" : "=f"(r.x), "=f"(r.y) : "l"(v)); return r;
}
__device__ __forceinline__ float ex2(float x) {
    float r; asm("ex2.approx.ftz.f32 %0, %1;" : "=f"(r) : "f"(x)); return r;
}

#define LOG2E 1.4426950408889634f

// ---------------- kernel: Q = X @ Wq  (4096x512 @ 512x512) ----------------
// block tile 128x128, 256 threads, 8x8 micro-tile, f32x2 packed FMA.
__global__ __launch_bounds__(256, 2) void gemm_q(const float* __restrict__ X,
                                                 const float* __restrict__ W) {
    __shared__ float Xs[32][128];   // k-major (transposed)
    __shared__ float Ws[32][128];   // natural
    int bid = blockIdx.x;
    int r0 = (bid >> 2) * 128;
    int c0 = (bid & 3) * 128;
    int tid = threadIdx.x;
    int tx = tid & 15, ty = tid >> 4;

    u64t acc[4][8];
#pragma unroll
    for (int p = 0; p < 4; p++)
#pragma unroll
        for (int j = 0; j < 8; j++) acc[p][j] = 0ull;

    for (int kc = 0; kc < 512; kc += 32) {
        __syncthreads();
        {   // load X tile, store transposed
            int i = tid & 127, kh = tid >> 7;
            const float4* src = (const float4*)(X + (size_t)(r0 + i) * 512 + kc + kh * 16);
#pragma unroll
            for (int q = 0; q < 4; q++) {
                float4 v = src[q];
                int k = kh * 16 + q * 4;
                Xs[k][i] = v.x; Xs[k + 1][i] = v.y; Xs[k + 2][i] = v.z; Xs[k + 3][i] = v.w;
            }
        }
        {   // load W tile (natural layout), coalesced float4
            int j = (tid & 31) * 4;
            int kb = tid >> 5;
#pragma unroll
            for (int q = 0; q < 4; q++) {
                int k = kb + q * 8;
                float4 v = *(const float4*)(W + (size_t)(kc + k) * 512 + c0 + j);
                *(float4*)&Ws[k][j] = v;
            }
        }
        __syncthreads();
#pragma unroll 4
        for (int k = 0; k < 32; k++) {
            u64t a2[4];
#pragma unroll
            for (int p = 0; p < 4; p++) a2[p] = *(const u64t*)&Xs[k][ty * 8 + 2 * p];
#pragma unroll
            for (int j = 0; j < 8; j++) {
                u64t b2 = bcast2(Ws[k][tx + 16 * j]);
#pragma unroll
                for (int p = 0; p < 4; p++) fma2(acc[p][j], a2[p], b2);
            }
        }
    }
#pragma unroll
    for (int p = 0; p < 4; p++) {
        int r = r0 + ty * 8 + 2 * p;
#pragma unroll
        for (int j = 0; j < 8; j++) {
            float2 v = u2f(acc[p][j]);
            g_Q[(size_t)r * 512 + c0 + tx + 16 * j] = v.x;
            g_Q[(size_t)(r + 1) * 512 + c0 + tx + 16 * j] = v.y;
        }
    }
}

// ---------------- tiny kernels: g, v ----------------
__global__ void calc_g(const float* __restrict__ W, const float* __restrict__ Wv) {
    int c = threadIdx.x;  // 512 threads
    float acc = 0.f;
    for (int k = 0; k < 512; k++) acc = fmaf(W[(size_t)k * 512 + c], Wv[k], acc);
    g_g[c] = acc;
}

__global__ void calc_v(const float* __restrict__ W) {
    int idx = blockIdx.x * blockDim.x + threadIdx.x;  // 4096
    int h = idx >> 9, i = idx & 511;
    float acc = 0.f;
#pragma unroll
    for (int j = 0; j < 64; j++)
        acc = fmaf(W[(size_t)i * 512 + h * 64 + j], g_g[h * 64 + j], acc);
    g_v[h * 512 + i] = acc;
}

// ---------------- row stats: norms (-> cn) and u ----------------
// one warp per row (b,s): 8 head-norms of Q and 8 dot products X.v_h
__global__ void rowstats(const float* __restrict__ X) {
    int warp = (blockIdx.x * blockDim.x + threadIdx.x) >> 5;
    int lane = threadIdx.x & 31;
    if (warp >= NROWS) return;
    int b = warp >> 11, s = warp & 2047;
    float sq[8], ua[8];
#pragma unroll
    for (int h = 0; h < 8; h++) { sq[h] = 0.f; ua[h] = 0.f; }
    const float* qrow = g_Q + (size_t)warp * 512;
    const float* xrow = X + (size_t)warp * 512;
#pragma unroll
    for (int m = 0; m < 16; m++) {
        int k = lane + 32 * m;
        float q = qrow[k];
        sq[m >> 1] = fmaf(q, q, sq[m >> 1]);   // head(k) = m/2, lane-independent
        float x = xrow[k];
#pragma unroll
        for (int h = 0; h < 8; h++) ua[h] = fmaf(x, g_v[h * 512 + k], ua[h]);
    }
#pragma unroll
    for (int h = 0; h < 8; h++) {
        float a = sq[h], u = ua[h];
#pragma unroll
        for (int o = 16; o > 0; o >>= 1) {
            a += __shfl_xor_sync(0xffffffffu, a, o);
            u += __shfl_xor_sync(0xffffffffu, u, o);
        }
        if (lane == 0) {
            int idx = (b * 8 + h) * 2048 + s;
            g_cn[idx] = -0.125f * LOG2E * sqrtf(a);
            g_u[idx] = u;
        }
    }
}

// ---------------- fused attention ----------------
// grid: 256 CTAs = (b,h) x s-tile(128). Per CTA: stream t in chunks of 128,
// compute 128x128 Gram tile in registers (f32x2), fold into unnormalized
// softmax accumulators (den, num) without materializing P.
#define ATTN_SMEM_FLOATS 16640   // Qs 8192 + Qt 8192 + cn 128 + uu 128
#define ATTN_SMEM_BYTES (ATTN_SMEM_FLOATS * 4)

__global__ __launch_bounds__(256, 2) void attn(float* __restrict__ out) {
    extern __shared__ float sm[];
    float* Qs = sm;              // [64][128] k-major
    float* Qt = sm + 8192;       // [64][128] k-major
    float* cn = sm + 16384;      // [128]
    float* uu = sm + 16512;      // [128]

    int bid = blockIdx.x;
    int stile = bid & 15;
    int bh = bid >> 4;
    int b = bh >> 3, h = bh & 7;
    int s0 = stile * 128;
    int tid = threadIdx.x;
    int tx = tid & 15, ty = tid >> 4;
    int bhS = bh * S_LEN;

    {   // load Qs tile once (transposed to k-major)
        int i = tid & 127, kh = tid >> 7;
        int row = b * S_LEN + s0 + i;
        const float4* src = (const float4*)(g_Q + (size_t)row * 512 + h * 64 + kh * 32);
#pragma unroll
        for (int q = 0; q < 8; q++) {
            float4 v = src[q];
            int k = kh * 32 + q * 4;
            Qs[k * 128 + i] = v.x; Qs[(k + 1) * 128 + i] = v.y;
            Qs[(k + 2) * 128 + i] = v.z; Qs[(k + 3) * 128 + i] = v.w;
        }
    }

    float den[8], num[8];
#pragma unroll
    for (int r = 0; r < 8; r++) { den[r] = 0.f; num[r] = 0.f; }

    const float C1 = 0.25f * LOG2E;

    for (int t0 = 0; t0 < S_LEN; t0 += 128) {
        __syncthreads();
        {   // load Qt chunk + cn + u
            int i = tid & 127, kh = tid >> 7;
            int row = b * S_LEN + t0 + i;
            const float4* src = (const float4*)(g_Q + (size_t)row * 512 + h * 64 + kh * 32);
#pragma unroll
            for (int q = 0; q < 8; q++) {
                float4 v = src[q];
                int k = kh * 32 + q * 4;
                Qt[k * 128 + i] = v.x; Qt[(k + 1) * 128 + i] = v.y;
                Qt[(k + 2) * 128 + i] = v.z; Qt[(k + 3) * 128 + i] = v.w;
            }
            if (kh == 0) {
                cn[i] = g_cn[bhS + t0 + i];
                uu[i] = g_u[bhS + t0 + i];
            }
        }
        __syncthreads();

        u64t acc[4][8];
#pragma unroll
        for (int p = 0; p < 4; p++)
#pragma unroll
            for (int j = 0; j < 8; j++) acc[p][j] = 0ull;

#pragma unroll 4
        for (int k = 0; k < 64; k++) {
            u64t a2[4];
#pragma unroll
            for (int p = 0; p < 4; p++) a2[p] = *(const u64t*)&Qs[k * 128 + ty * 8 + 2 * p];
#pragma unroll
            for (int j = 0; j < 8; j++) {
                u64t b2 = bcast2(Qt[k * 128 + tx + 16 * j]);
#pragma unroll
                for (int p = 0; p < 4; p++) fma2(acc[p][j], a2[p], b2);
            }
        }

        // fold Gram tile into softmax accumulators (no max needed: logits bounded)
        float cl[8], ul[8];
#pragma unroll
        for (int j = 0; j < 8; j++) { cl[j] = cn[tx + 16 * j]; ul[j] = uu[tx + 16 * j]; }
#pragma unroll
        for (int p = 0; p < 4; p++) {
#pragma unroll
            for (int j = 0; j < 8; j++) {
                float2 dv = u2f(acc[p][j]);
                float w0 = ex2(fmaf(dv.x, C1, cl[j]));
                float w1 = ex2(fmaf(dv.y, C1, cl[j]));
                den[2 * p]     += w0;
                num[2 * p]      = fmaf(w0, ul[j], num[2 * p]);
                den[2 * p + 1] += w1;
                num[2 * p + 1]  = fmaf(w1, ul[j], num[2 * p + 1]);
            }
        }
    }

    // cross-tx reduction (16 partials per row), reuse smem
    __syncthreads();
    float* dred = sm;                // [128][17] padded
    float* nred = sm + 128 * 17;     // [128][17]
#pragma unroll
    for (int r = 0; r < 8; r++) {
        int row = ty * 8 + r;
        dred[row * 17 + tx] = den[r];
        nred[row * 17 + tx] = num[r];
    }
    __syncthreads();
    if (tid < 128) {
        float ds = 0.f, ns = 0.f;
#pragma unroll
        for (int i = 0; i < 16; i++) {
            ds += dred[tid * 17 + i];
            ns += nred[tid * 17 + i];
        }
        float z = ns / ds;
        out[bhS + s0 + tid] = 1.0f / (1.0f + ex2(-z * LOG2E));
    }
}

// ---------------- launch ----------------
extern "C" void kernel_launch(void* const* d_in, const int* in_sizes, int n_in,
                              void* d_out, int out_size) {
    const float *X = nullptr, *Wq = nullptr, *Wv = nullptr;
    for (int i = 0; i < n_in; i++) {
        if (in_sizes[i] == 2 * 2048 * 512)      X  = (const float*)d_in[i];
        else if (in_sizes[i] == 512 * 512)      Wq = (const float*)d_in[i];
        else if (in_sizes[i] == 512)            Wv = (const float*)d_in[i];
    }
    float* out = (float*)d_out;

    cudaFuncSetAttribute(attn, cudaFuncAttributeMaxDynamicSharedMemorySize, ATTN_SMEM_BYTES);

    gemm_q<<<128, 256>>>(X, Wq);
    calc_g<<<1, 512>>>(Wq, Wv);
    calc_v<<<16, 256>>>(Wq);
    rowstats<<<512, 256>>>(X);
    attn<<<256, 256, ATTN_SMEM_BYTES>>>(out);
}

// round 3
// speedup vs baseline: 1.7908x; 1.7908x over previous
#include <cuda_runtime.h>
#include <cuda_bf16.h>
#include <cstdint>

#define S_LEN 2048
#define D_DIM 512
#define NH 8
#define NROWS 4096   // B*S
#define NBH 16       // B*H

typedef unsigned long long u64t;

// ---------------- scratch (static device globals; no allocs) ----------------
__device__ float g_Q[NROWS * D_DIM];                     // X @ Wq, row-major
__device__ float g_g[D_DIM];
__device__ float g_v[NH * D_DIM];
__device__ float2 g_cu[NBH * S_LEN];                     // {cn, u} per (bh, t)
__device__ __align__(128) __nv_bfloat16 g_Qhi[NBH * S_LEN * 64];  // head-major
__device__ __align__(128) __nv_bfloat16 g_Qlo[NBH * S_LEN * 64];

// ---------------- helpers ----------------
__device__ __forceinline__ void fma2(u64t& d, u64t a, u64t b) {
    asm("fma.rn.f32x2 %0, %1, %2, %0;" : "+l"(d) : "l"(a), "l"(b));
}
__device__ __forceinline__ u64t bcast2(float x) {
    u64t r; asm("mov.b64 %0, {%1, %1};" : "=l"(r) : "f"(x)); return r;
}
__device__ __forceinline__ float2 u2f(u64t v) {
    float2 r; asm("mov.b64 {%0, %1}, %2;" : "=f"(r.x), "=f"(r.y) : "l"(v)); return r;
}
__device__ __forceinline__ float ex2(float x) {
    float r; asm("ex2.approx.ftz.f32 %0, %1;" : "=f"(r) : "f"(x)); return r;
}
__device__ __forceinline__ uint32_t smem_u32(const void* p) {
    uint32_t a;
    asm("{ .reg .u64 t; cvta.to.shared.u64 t, %1; cvt.u32.u64 %0, t; }" : "=r"(a) : "l"(p));
    return a;
}
#define LOG2E 1.4426950408889634f
#define SW128(o) ((o) ^ ((((uint32_t)(o)) >> 3) & 0x70))

__device__ __forceinline__ void ldsm4(uint32_t* r, uint32_t addr) {
    asm volatile("ldmatrix.sync.aligned.m8n8.x4.shared.b16 {%0,%1,%2,%3}, [%4];"
                 : "=r"(r[0]), "=r"(r[1]), "=r"(r[2]), "=r"(r[3]) : "r"(addr));
}
__device__ __forceinline__ void mma16816(float* c, const uint32_t* a, const uint32_t* b) {
    asm volatile("mma.sync.aligned.m16n8k16.row.col.f32.bf16.bf16.f32 "
                 "{%0,%1,%2,%3}, {%4,%5,%6,%7}, {%8,%9}, {%0,%1,%2,%3};"
                 : "+f"(c[0]), "+f"(c[1]), "+f"(c[2]), "+f"(c[3])
                 : "r"(a[0]), "r"(a[1]), "r"(a[2]), "r"(a[3]), "r"(b[0]), "r"(b[1]));
}

// ---------------- kernel: Q = X @ Wq  (4096x512 @ 512x512) ----------------
__global__ __launch_bounds__(256, 2) void gemm_q(const float* __restrict__ X,
                                                 const float* __restrict__ W) {
    __shared__ float Xs[32][128];
    __shared__ float Ws[32][128];
    int bid = blockIdx.x;
    int r0 = (bid >> 2) * 128;
    int c0 = (bid & 3) * 128;
    int tid = threadIdx.x;
    int tx = tid & 15, ty = tid >> 4;

    u64t acc[4][8];
#pragma unroll
    for (int p = 0; p < 4; p++)
#pragma unroll
        for (int j = 0; j < 8; j++) acc[p][j] = 0ull;

    for (int kc = 0; kc < 512; kc += 32) {
        __syncthreads();
        {
            int i = tid & 127, kh = tid >> 7;
            const float4* src = (const float4*)(X + (size_t)(r0 + i) * 512 + kc + kh * 16);
#pragma unroll
            for (int q = 0; q < 4; q++) {
                float4 v = src[q];
                int k = kh * 16 + q * 4;
                Xs[k][i] = v.x; Xs[k + 1][i] = v.y; Xs[k + 2][i] = v.z; Xs[k + 3][i] = v.w;
            }
        }
        {
            int j = (tid & 31) * 4;
            int kb = tid >> 5;
#pragma unroll
            for (int q = 0; q < 4; q++) {
                int k = kb + q * 8;
                float4 v = *(const float4*)(W + (size_t)(kc + k) * 512 + c0 + j);
                *(float4*)&Ws[k][j] = v;
            }
        }
        __syncthreads();
#pragma unroll 4
        for (int k = 0; k < 32; k++) {
            u64t a2[4];
#pragma unroll
            for (int p = 0; p < 4; p++) a2[p] = *(const u64t*)&Xs[k][ty * 8 + 2 * p];
#pragma unroll
            for (int j = 0; j < 8; j++) {
                u64t b2 = bcast2(Ws[k][tx + 16 * j]);
#pragma unroll
                for (int p = 0; p < 4; p++) fma2(acc[p][j], a2[p], b2);
            }
        }
    }
#pragma unroll
    for (int p = 0; p < 4; p++) {
        int r = r0 + ty * 8 + 2 * p;
#pragma unroll
        for (int j = 0; j < 8; j++) {
            float2 v = u2f(acc[p][j]);
            g_Q[(size_t)r * 512 + c0 + tx + 16 * j] = v.x;
            g_Q[(size_t)(r + 1) * 512 + c0 + tx + 16 * j] = v.y;
        }
    }
}

// ---------------- tiny kernels: g, v ----------------
__global__ void calc_g(const float* __restrict__ W, const float* __restrict__ Wv) {
    int c = threadIdx.x;
    float acc = 0.f;
    for (int k = 0; k < 512; k++) acc = fmaf(W[(size_t)k * 512 + c], Wv[k], acc);
    g_g[c] = acc;
}

__global__ void calc_v(const float* __restrict__ W) {
    int idx = blockIdx.x * blockDim.x + threadIdx.x;
    int h = idx >> 9, i = idx & 511;
    float acc = 0.f;
#pragma unroll
    for (int j = 0; j < 64; j++)
        acc = fmaf(W[(size_t)i * 512 + h * 64 + j], g_g[h * 64 + j], acc);
    g_v[h * 512 + i] = acc;
}

// ---------------- row stats: {cn, u} per (b,h,t) ----------------
__global__ void rowstats(const float* __restrict__ X) {
    int warp = (blockIdx.x * blockDim.x + threadIdx.x) >> 5;
    int lane = threadIdx.x & 31;
    if (warp >= NROWS) return;
    int b = warp >> 11, s = warp & 2047;
    float sq[8], ua[8];
#pragma unroll
    for (int h = 0; h < 8; h++) { sq[h] = 0.f; ua[h] = 0.f; }
    const float* qrow = g_Q + (size_t)warp * 512;
    const float* xrow = X + (size_t)warp * 512;
#pragma unroll
    for (int m = 0; m < 16; m++) {
        int k = lane + 32 * m;
        float q = qrow[k];
        sq[m >> 1] = fmaf(q, q, sq[m >> 1]);
        float x = xrow[k];
#pragma unroll
        for (int h = 0; h < 8; h++) ua[h] = fmaf(x, g_v[h * 512 + k], ua[h]);
    }
#pragma unroll
    for (int h = 0; h < 8; h++) {
        float a = sq[h], u = ua[h];
#pragma unroll
        for (int o = 16; o > 0; o >>= 1) {
            a += __shfl_xor_sync(0xffffffffu, a, o);
            u += __shfl_xor_sync(0xffffffffu, u, o);
        }
        if (lane == 0) {
            int idx = (b * 8 + h) * 2048 + s;
            g_cu[idx] = make_float2(-0.125f * LOG2E * sqrtf(a), u);
        }
    }
}

// ---------------- convert Q -> head-major bf16 hi/lo ----------------
__global__ void convert_q() {
    int warp = (blockIdx.x * blockDim.x + threadIdx.x) >> 5;  // 4096 rows
    int lane = threadIdx.x & 31;
    if (warp >= NROWS) return;
    int b = warp >> 11, s = warp & 2047;
    const float* src = g_Q + (size_t)warp * 512;
#pragma unroll
    for (int m = 0; m < 16; m++) {
        int k = lane + 32 * m;
        float v = src[k];
        __nv_bfloat16 hi = __float2bfloat16(v);
        __nv_bfloat16 lo = __float2bfloat16(v - __bfloat162float(hi));
        size_t dst = ((size_t)(b * 8 + (m >> 1)) * 2048 + s) * 64 + (k & 63);
        g_Qhi[dst] = hi;
        g_Qlo[dst] = lo;
    }
}

// ---------------- fused attention (mma.sync bf16 hi/lo split) ----------------
// smem (bytes): QsHi 16K | QsLo 16K | QtHi 16K | QtLo 16K | cu 1K  = 66560
#define OFF_QSHI 0
#define OFF_QSLO 16384
#define OFF_QTHI 32768
#define OFF_QTLO 49152
#define OFF_CU   65536
#define ATTN_SMEM_BYTES 66560

__global__ __launch_bounds__(256, 2) void attn(float* __restrict__ out) {
    extern __shared__ char sm[];
    uint32_t sb = smem_u32(sm);
    int tid = threadIdx.x;
    int lane = tid & 31, w = tid >> 5;
    int bid = blockIdx.x;
    int stile = bid & 15;
    int bh = bid >> 4;
    int s0 = stile * 128;
    int bhS = bh * S_LEN;
    float2* scu = (float2*)(sm + OFF_CU);

    // ---- load Qs (s-tile) hi/lo into swizzled smem ----
    {
        const uint4* shi = (const uint4*)(g_Qhi + ((size_t)bhS + s0) * 64);
        const uint4* slo = (const uint4*)(g_Qlo + ((size_t)bhS + s0) * 64);
#pragma unroll
        for (int q = 0; q < 4; q++) {
            uint32_t idx = (uint32_t)(q * 256 + tid);
            uint32_t off = idx * 16;
            uint32_t so = SW128(off);
            *(uint4*)(sm + OFF_QSHI + so) = shi[idx];
            *(uint4*)(sm + OFF_QSLO + so) = slo[idx];
        }
    }

    // ldmatrix address components
    int row_a = w * 16 + (lane & 15);
    uint32_t a_sw = (uint32_t)((row_a & 7) << 4);
    uint32_t a_hi16 = (uint32_t)((lane >> 4) * 16);
    uint32_t aBaseHi = sb + OFF_QSHI + (uint32_t)row_a * 128;
    uint32_t aBaseLo = sb + OFF_QSLO + (uint32_t)row_a * 128;
    int nrow_base = (lane & 7) + ((lane >> 4) << 3);  // + nb*16
    uint32_t b_sw = (uint32_t)((lane & 7) << 4);
    uint32_t b_c16 = (uint32_t)(((lane >> 3) & 1) * 16);

    const float C1 = 0.25f * LOG2E;
    float den0 = 0.f, num0 = 0.f, den1 = 0.f, num1 = 0.f;

    for (int t0 = 0; t0 < S_LEN; t0 += 128) {
        __syncthreads();   // previous epilogue done: Qt buffers + scu free
        {
            const uint4* thi = (const uint4*)(g_Qhi + ((size_t)bhS + t0) * 64);
            const uint4* tlo = (const uint4*)(g_Qlo + ((size_t)bhS + t0) * 64);
#pragma unroll
            for (int q = 0; q < 4; q++) {
                uint32_t idx = (uint32_t)(q * 256 + tid);
                uint32_t so = SW128(idx * 16);
                *(uint4*)(sm + OFF_QTHI + so) = thi[idx];
                *(uint4*)(sm + OFF_QTLO + so) = tlo[idx];
            }
            if (tid < 128) scu[tid] = g_cu[bhS + t0 + tid];
        }
        __syncthreads();

        float cacc[16][4];
#pragma unroll
        for (int nb = 0; nb < 16; nb++)
#pragma unroll
            for (int r = 0; r < 4; r++) cacc[nb][r] = 0.f;

#pragma unroll
        for (int kk = 0; kk < 4; kk++) {
            uint32_t acol = ((uint32_t)(kk * 32) + a_hi16) ^ a_sw;
            uint32_t ahi[4], alo[4];
            ldsm4(ahi, aBaseHi + acol);
            ldsm4(alo, aBaseLo + acol);
            uint32_t bcol = ((uint32_t)(kk * 32) + b_c16) ^ b_sw;
#pragma unroll
            for (int nb2 = 0; nb2 < 8; nb2++) {
                uint32_t nrow = (uint32_t)(nrow_base + nb2 * 16);
                uint32_t boff = nrow * 128 + bcol;
                uint32_t bhi[4], blo[4];
                ldsm4(bhi, sb + OFF_QTHI + boff);
                ldsm4(blo, sb + OFF_QTLO + boff);
                // nblk = 2*nb2 uses regs {0,1}; nblk = 2*nb2+1 uses {2,3}
                mma16816(cacc[2 * nb2],     ahi, bhi);
                mma16816(cacc[2 * nb2],     ahi, blo);
                mma16816(cacc[2 * nb2],     alo, bhi);
                mma16816(cacc[2 * nb2 + 1], ahi, bhi + 2);
                mma16816(cacc[2 * nb2 + 1], ahi, blo + 2);
                mma16816(cacc[2 * nb2 + 1], alo, bhi + 2);
            }
        }

        // ---- fold Gram tile into softmax accumulators ----
#pragma unroll
        for (int nb = 0; nb < 16; nb++) {
            int col0 = nb * 8 + (lane & 3) * 2;
            float2 cuA = scu[col0];
            float2 cuB = scu[col0 + 1];
            float w0 = ex2(fmaf(cacc[nb][0], C1, cuA.x));
            float w1 = ex2(fmaf(cacc[nb][1], C1, cuB.x));
            float w2 = ex2(fmaf(cacc[nb][2], C1, cuA.x));
            float w3 = ex2(fmaf(cacc[nb][3], C1, cuB.x));
            den0 += w0; num0 = fmaf(w0, cuA.y, num0);
            den0 += w1; num0 = fmaf(w1, cuB.y, num0);
            den1 += w2; num1 = fmaf(w2, cuA.y, num1);
            den1 += w3; num1 = fmaf(w3, cuB.y, num1);
        }
    }

    // quad reduction (lanes sharing a C row differ in lane&3)
#pragma unroll
    for (int o = 1; o <= 2; o <<= 1) {
        den0 += __shfl_xor_sync(0xffffffffu, den0, o);
        num0 += __shfl_xor_sync(0xffffffffu, num0, o);
        den1 += __shfl_xor_sync(0xffffffffu, den1, o);
        num1 += __shfl_xor_sync(0xffffffffu, num1, o);
    }
    if ((lane & 3) == 0) {
        int gr = lane >> 2;
        int r0 = w * 16 + gr;
        float z0 = num0 / den0;
        float z1 = num1 / den1;
        out[bhS + s0 + r0]     = 1.0f / (1.0f + ex2(-z0 * LOG2E));
        out[bhS + s0 + r0 + 8] = 1.0f / (1.0f + ex2(-z1 * LOG2E));
    }
}

// ---------------- launch ----------------
extern "C" void kernel_launch(void* const* d_in, const int* in_sizes, int n_in,
                              void* d_out, int out_size) {
    const float *X = nullptr, *Wq = nullptr, *Wv = nullptr;
    for (int i = 0; i < n_in; i++) {
        if (in_sizes[i] == 2 * 2048 * 512)      X  = (const float*)d_in[i];
        else if (in_sizes[i] == 512 * 512)      Wq = (const float*)d_in[i];
        else if (in_sizes[i] == 512)            Wv = (const float*)d_in[i];
    }
    float* out = (float*)d_out;

    cudaFuncSetAttribute(attn, cudaFuncAttributeMaxDynamicSharedMemorySize, ATTN_SMEM_BYTES);

    gemm_q<<<128, 256>>>(X, Wq);
    calc_g<<<1, 512>>>(Wq, Wv);
    calc_v<<<16, 256>>>(Wq);
    rowstats<<<512, 256>>>(X);
    convert_q<<<512, 256>>>();
    attn<<<256, 256, ATTN_SMEM_BYTES>>>(out);
}

// round 4
// speedup vs baseline: 1.8982x; 1.0600x over previous
#include <cuda_runtime.h>
#include <cuda_bf16.h>
#include <cstdint>

#define S_LEN 2048
#define D_DIM 512
#define NH 8
#define NROWS 4096   // B*S
#define NBH 16       // B*H

typedef unsigned long long u64t;

// ---------------- scratch (static device globals; no allocs) ----------------
__device__ float g_g[D_DIM];
__device__ float g_v[NH * D_DIM];
__device__ float2 g_cu[NBH * S_LEN];                     // {cn, u} per (bh, t)
__device__ __align__(128) __nv_bfloat16 g_Qhi[NBH * S_LEN * 64];  // head-major
__device__ __align__(128) __nv_bfloat16 g_Qlo[NBH * S_LEN * 64];

// ---------------- helpers ----------------
__device__ __forceinline__ void fma2(u64t& d, u64t a, u64t b) {
    asm("fma.rn.f32x2 %0, %1, %2, %0;" : "+l"(d) : "l"(a), "l"(b));
}
__device__ __forceinline__ u64t bcast2(float x) {
    u64t r; asm("mov.b64 %0, {%1, %1};" : "=l"(r) : "f"(x)); return r;
}
__device__ __forceinline__ float2 u2f(u64t v) {
    float2 r; asm("mov.b64 {%0, %1}, %2;" : "=f"(r.x), "=f"(r.y) : "l"(v)); return r;
}
__device__ __forceinline__ float ex2(float x) {
    float r; asm("ex2.approx.ftz.f32 %0, %1;" : "=f"(r) : "f"(x)); return r;
}
__device__ __forceinline__ uint32_t smem_u32(const void* p) {
    uint32_t a;
    asm("{ .reg .u64 t; cvta.to.shared.u64 t, %1; cvt.u32.u64 %0, t; }" : "=r"(a) : "l"(p));
    return a;
}
#define LOG2E 1.4426950408889634f
#define SW128(o) ((o) ^ ((((uint32_t)(o)) >> 3) & 0x70))

__device__ __forceinline__ void ldsm4(uint32_t* r, uint32_t addr) {
    asm volatile("ldmatrix.sync.aligned.m8n8.x4.shared.b16 {%0,%1,%2,%3}, [%4];"
                 : "=r"(r[0]), "=r"(r[1]), "=r"(r[2]), "=r"(r[3]) : "r"(addr));
}
__device__ __forceinline__ void mma16816(float* c, const uint32_t* a, const uint32_t* b) {
    asm volatile("mma.sync.aligned.m16n8k16.row.col.f32.bf16.bf16.f32 "
                 "{%0,%1,%2,%3}, {%4,%5,%6,%7}, {%8,%9}, {%0,%1,%2,%3};"
                 : "+f"(c[0]), "+f"(c[1]), "+f"(c[2]), "+f"(c[3])
                 : "r"(a[0]), "r"(a[1]), "r"(a[2]), "r"(a[3]), "r"(b[0]), "r"(b[1]));
}
__device__ __forceinline__ void cp16(uint32_t dst, const void* src) {
    asm volatile("cp.async.cg.shared.global [%0], [%1], 16;" :: "r"(dst), "l"(src));
}
__device__ __forceinline__ void cp_commit() {
    asm volatile("cp.async.commit_group;" ::: "memory");
}
template <int N>
__device__ __forceinline__ void cp_wait() {
    asm volatile("cp.async.wait_group %0;" :: "n"(N) : "memory");
}

// ---------------- kernel: Q = X @ Wq, fused norm + bf16 hi/lo emit ----------------
__global__ __launch_bounds__(256, 2) void gemm_q(const float* __restrict__ X,
                                                 const float* __restrict__ W) {
    __shared__ float Xs[32][128];
    __shared__ float Ws[32][128];
    int bid = blockIdx.x;
    int r0 = (bid >> 2) * 128;
    int c0 = (bid & 3) * 128;
    int tid = threadIdx.x;
    int tx = tid & 15, ty = tid >> 4;

    u64t acc[4][8];
#pragma unroll
    for (int p = 0; p < 4; p++)
#pragma unroll
        for (int j = 0; j < 8; j++) acc[p][j] = 0ull;

    for (int kc = 0; kc < 512; kc += 32) {
        __syncthreads();
        {
            int i = tid & 127, kh = tid >> 7;
            const float4* src = (const float4*)(X + (size_t)(r0 + i) * 512 + kc + kh * 16);
#pragma unroll
            for (int q = 0; q < 4; q++) {
                float4 v = src[q];
                int k = kh * 16 + q * 4;
                Xs[k][i] = v.x; Xs[k + 1][i] = v.y; Xs[k + 2][i] = v.z; Xs[k + 3][i] = v.w;
            }
        }
        {
            int j = (tid & 31) * 4;
            int kb = tid >> 5;
#pragma unroll
            for (int q = 0; q < 4; q++) {
                int k = kb + q * 8;
                float4 v = *(const float4*)(W + (size_t)(kc + k) * 512 + c0 + j);
                *(float4*)&Ws[k][j] = v;
            }
        }
        __syncthreads();
#pragma unroll 4
        for (int k = 0; k < 32; k++) {
            u64t a2[4];
#pragma unroll
            for (int p = 0; p < 4; p++) a2[p] = *(const u64t*)&Xs[k][ty * 8 + 2 * p];
#pragma unroll
            for (int j = 0; j < 8; j++) {
                u64t b2 = bcast2(Ws[k][tx + 16 * j]);
#pragma unroll
                for (int p = 0; p < 4; p++) fma2(acc[p][j], a2[p], b2);
            }
        }
    }

    // ---- fused epilogue: per-head norms + bf16 hi/lo emit (staged via smem) ----
    int b = r0 >> 11;
    int srow0 = r0 & 2047;
    __nv_bfloat16* sHi = (__nv_bfloat16*)Xs;   // 128x64 bf16 = 16KB
    __nv_bfloat16* sLo = (__nv_bfloat16*)Ws;

#pragma unroll
    for (int hx = 0; hx < 2; hx++) {
        int h = (c0 >> 6) + hx;
        __syncthreads();   // staging buffers free
        float s2[8];
#pragma unroll
        for (int r = 0; r < 8; r++) s2[r] = 0.f;
#pragma unroll
        for (int p = 0; p < 4; p++) {
#pragma unroll
            for (int jj = 0; jj < 4; jj++) {
                float2 v = u2f(acc[p][hx * 4 + jj]);
                int col = tx + 16 * jj;
                int row0 = ty * 8 + 2 * p;
                __nv_bfloat16 hx0 = __float2bfloat16(v.x);
                __nv_bfloat16 lx0 = __float2bfloat16(v.x - __bfloat162float(hx0));
                __nv_bfloat16 hx1 = __float2bfloat16(v.y);
                __nv_bfloat16 lx1 = __float2bfloat16(v.y - __bfloat162float(hx1));
                sHi[row0 * 64 + col] = hx0; sLo[row0 * 64 + col] = lx0;
                sHi[(row0 + 1) * 64 + col] = hx1; sLo[(row0 + 1) * 64 + col] = lx1;
                s2[2 * p] = fmaf(v.x, v.x, s2[2 * p]);
                s2[2 * p + 1] = fmaf(v.y, v.y, s2[2 * p + 1]);
            }
        }
        // reduce across tx (lane bits 0-3)
#pragma unroll
        for (int r = 0; r < 8; r++) {
            float v = s2[r];
#pragma unroll
            for (int o = 1; o <= 8; o <<= 1) v += __shfl_xor_sync(0xffffffffu, v, o);
            if (tx == 0) {
                int srow = srow0 + ty * 8 + r;
                g_cu[(b * 8 + h) * S_LEN + srow].x = -0.125f * LOG2E * sqrtf(v);
            }
        }
        __syncthreads();
        // coalesced copy staging -> global (16KB each)
        uint4* dstH = (uint4*)(g_Qhi + ((size_t)(b * 8 + h) * S_LEN + srow0) * 64);
        uint4* dstL = (uint4*)(g_Qlo + ((size_t)(b * 8 + h) * S_LEN + srow0) * 64);
        const uint4* sH4 = (const uint4*)sHi;
        const uint4* sL4 = (const uint4*)sLo;
#pragma unroll
        for (int q = 0; q < 4; q++) {
            dstH[q * 256 + tid] = sH4[q * 256 + tid];
            dstL[q * 256 + tid] = sL4[q * 256 + tid];
        }
    }
}

// ---------------- tiny kernels: g, v ----------------
__global__ void calc_g(const float* __restrict__ W, const float* __restrict__ Wv) {
    int c = threadIdx.x;
    float acc = 0.f;
    for (int k = 0; k < 512; k++) acc = fmaf(W[(size_t)k * 512 + c], Wv[k], acc);
    g_g[c] = acc;
}

__global__ void calc_v(const float* __restrict__ W) {
    int idx = blockIdx.x * blockDim.x + threadIdx.x;
    int h = idx >> 9, i = idx & 511;
    float acc = 0.f;
#pragma unroll
    for (int j = 0; j < 64; j++)
        acc = fmaf(W[(size_t)i * 512 + h * 64 + j], g_g[h * 64 + j], acc);
    g_v[h * 512 + i] = acc;
}

// ---------------- u[b,h,t] = X[b,t,:] . v[h] ----------------
__global__ __launch_bounds__(256) void calc_u(const float* __restrict__ X) {
    __shared__ float sv[NH * 512];   // 16KB
    int tid = threadIdx.x;
    for (int i = tid; i < NH * 512; i += 256) sv[i] = g_v[i];
    __syncthreads();
    int warp = blockIdx.x * 8 + (tid >> 5);
    int lane = tid & 31;
    int b = warp >> 11, s = warp & 2047;
    const float* xrow = X + (size_t)warp * 512;
    float ua[8];
#pragma unroll
    for (int h = 0; h < 8; h++) ua[h] = 0.f;
#pragma unroll
    for (int m = 0; m < 16; m++) {
        int k = lane + 32 * m;
        float x = xrow[k];
#pragma unroll
        for (int h = 0; h < 8; h++) ua[h] = fmaf(x, sv[h * 512 + k], ua[h]);
    }
#pragma unroll
    for (int h = 0; h < 8; h++) {
        float u = ua[h];
#pragma unroll
        for (int o = 16; o > 0; o >>= 1) u += __shfl_xor_sync(0xffffffffu, u, o);
        if (lane == 0) g_cu[(b * 8 + h) * S_LEN + s].y = u;
    }
}

// ---------------- fused attention (mma.sync bf16 hi/lo, cp.async 2-stage) ----
// smem: QsHi 16K | QsLo 16K | Qt[2] 32K each (hi+lo) | cu[2] 1K each = 100352 B
#define OFF_QSHI 0
#define OFF_QSLO 16384
#define OFF_QT   32768
#define OFF_CU   98304
#define ATTN_SMEM_BYTES 100352

__global__ __launch_bounds__(256, 2) void attn(float* __restrict__ out) {
    extern __shared__ char sm[];
    uint32_t sb = smem_u32(sm);
    int tid = threadIdx.x;
    int lane = tid & 31, w = tid >> 5;
    int bid = blockIdx.x;
    int stile = bid & 15;
    int bh = bid >> 4;
    int s0 = stile * 128;
    int bhS = bh * S_LEN;

    const __nv_bfloat16* qhiB = g_Qhi + (size_t)bhS * 64;
    const __nv_bfloat16* qloB = g_Qlo + (size_t)bhS * 64;

    // ---- load Qs (resident) ----
    {
        const uint4* shi = (const uint4*)(qhiB + (size_t)s0 * 64);
        const uint4* slo = (const uint4*)(qloB + (size_t)s0 * 64);
#pragma unroll
        for (int q = 0; q < 4; q++) {
            uint32_t idx = (uint32_t)(q * 256 + tid);
            uint32_t so = SW128(idx * 16);
            *(uint4*)(sm + OFF_QSHI + so) = shi[idx];
            *(uint4*)(sm + OFF_QSLO + so) = slo[idx];
        }
    }

    // ---- prefetch tile 0 ----
    {
        const uint4* thi = (const uint4*)qhiB;
        const uint4* tlo = (const uint4*)qloB;
#pragma unroll
        for (int q = 0; q < 4; q++) {
            uint32_t idx = (uint32_t)(q * 256 + tid);
            uint32_t so = SW128(idx * 16);
            cp16(sb + OFF_QT + so, thi + idx);
            cp16(sb + OFF_QT + 16384 + so, tlo + idx);
        }
        if (tid < 64) cp16(sb + OFF_CU + tid * 16, (const char*)(g_cu + bhS) + tid * 16);
        cp_commit();
    }

    // ldmatrix address components
    int row_a = w * 16 + (lane & 15);
    uint32_t a_sw = (uint32_t)((row_a & 7) << 4);
    uint32_t a_hi16 = (uint32_t)((lane >> 4) * 16);
    uint32_t aBaseHi = sb + OFF_QSHI + (uint32_t)row_a * 128;
    uint32_t aBaseLo = sb + OFF_QSLO + (uint32_t)row_a * 128;
    int nrow_base = (lane & 7) + ((lane >> 4) << 3);
    uint32_t b_sw = (uint32_t)((lane & 7) << 4);
    uint32_t b_c16 = (uint32_t)(((lane >> 3) & 1) * 16);

    const float C1 = 0.25f * LOG2E;
    float den0 = 0.f, num0 = 0.f, den1 = 0.f, num1 = 0.f;

    for (int it = 0; it < 16; it++) {
        int buf = it & 1;
        __syncthreads();   // prior compute on buf^1 done everywhere
        if (it < 15) {
            int t1 = (it + 1) * 128;
            const uint4* thi = (const uint4*)(qhiB + (size_t)t1 * 64);
            const uint4* tlo = (const uint4*)(qloB + (size_t)t1 * 64);
            uint32_t base = sb + OFF_QT + (buf ^ 1) * 32768;
#pragma unroll
            for (int q = 0; q < 4; q++) {
                uint32_t idx = (uint32_t)(q * 256 + tid);
                uint32_t so = SW128(idx * 16);
                cp16(base + so, thi + idx);
                cp16(base + 16384 + so, tlo + idx);
            }
            if (tid < 64)
                cp16(sb + OFF_CU + (buf ^ 1) * 1024 + tid * 16,
                     (const char*)(g_cu + bhS + t1) + tid * 16);
            cp_commit();
            cp_wait<1>();
        } else {
            cp_wait<0>();
        }
        __syncthreads();

        uint32_t btHi = sb + OFF_QT + buf * 32768;
        uint32_t btLo = btHi + 16384;
        const float2* scu = (const float2*)(sm + OFF_CU + buf * 1024);

        float cacc[16][4];
#pragma unroll
        for (int nb = 0; nb < 16; nb++)
#pragma unroll
            for (int r = 0; r < 4; r++) cacc[nb][r] = 0.f;

#pragma unroll
        for (int kk = 0; kk < 4; kk++) {
            uint32_t acol = ((uint32_t)(kk * 32) + a_hi16) ^ a_sw;
            uint32_t ahi[4], alo[4];
            ldsm4(ahi, aBaseHi + acol);
            ldsm4(alo, aBaseLo + acol);
            uint32_t bcol = ((uint32_t)(kk * 32) + b_c16) ^ b_sw;
#pragma unroll
            for (int nb2 = 0; nb2 < 8; nb2++) {
                uint32_t boff = (uint32_t)(nrow_base + nb2 * 16) * 128 + bcol;
                uint32_t bhi[4], blo[4];
                ldsm4(bhi, btHi + boff);
                ldsm4(blo, btLo + boff);
                mma16816(cacc[2 * nb2],     ahi, bhi);
                mma16816(cacc[2 * nb2],     ahi, blo);
                mma16816(cacc[2 * nb2],     alo, bhi);
                mma16816(cacc[2 * nb2 + 1], ahi, bhi + 2);
                mma16816(cacc[2 * nb2 + 1], ahi, blo + 2);
                mma16816(cacc[2 * nb2 + 1], alo, bhi + 2);
            }
        }

        // ---- fold Gram tile into softmax accumulators ----
#pragma unroll
        for (int nb = 0; nb < 16; nb++) {
            int col0 = nb * 8 + (lane & 3) * 2;
            float2 cuA = scu[col0];
            float2 cuB = scu[col0 + 1];
            float w0 = ex2(fmaf(cacc[nb][0], C1, cuA.x));
            float w1 = ex2(fmaf(cacc[nb][1], C1, cuB.x));
            float w2 = ex2(fmaf(cacc[nb][2], C1, cuA.x));
            float w3 = ex2(fmaf(cacc[nb][3], C1, cuB.x));
            den0 += w0; num0 = fmaf(w0, cuA.y, num0);
            den0 += w1; num0 = fmaf(w1, cuB.y, num0);
            den1 += w2; num1 = fmaf(w2, cuA.y, num1);
            den1 += w3; num1 = fmaf(w3, cuB.y, num1);
        }
    }

    // quad reduction
#pragma unroll
    for (int o = 1; o <= 2; o <<= 1) {
        den0 += __shfl_xor_sync(0xffffffffu, den0, o);
        num0 += __shfl_xor_sync(0xffffffffu, num0, o);
        den1 += __shfl_xor_sync(0xffffffffu, den1, o);
        num1 += __shfl_xor_sync(0xffffffffu, num1, o);
    }
    if ((lane & 3) == 0) {
        int gr = lane >> 2;
        int r0 = w * 16 + gr;
        float z0 = num0 / den0;
        float z1 = num1 / den1;
        out[bhS + s0 + r0]     = 1.0f / (1.0f + ex2(-z0 * LOG2E));
        out[bhS + s0 + r0 + 8] = 1.0f / (1.0f + ex2(-z1 * LOG2E));
    }
}

// ---------------- launch ----------------
extern "C" void kernel_launch(void* const* d_in, const int* in_sizes, int n_in,
                              void* d_out, int out_size) {
    const float *X = nullptr, *Wq = nullptr, *Wv = nullptr;
    for (int i = 0; i < n_in; i++) {
        if (in_sizes[i] == 2 * 2048 * 512)      X  = (const float*)d_in[i];
        else if (in_sizes[i] == 512 * 512)      Wq = (const float*)d_in[i];
        else if (in_sizes[i] == 512)            Wv = (const float*)d_in[i];
    }
    float* out = (float*)d_out;

    cudaFuncSetAttribute(attn, cudaFuncAttributeMaxDynamicSharedMemorySize, ATTN_SMEM_BYTES);

    gemm_q<<<128, 256>>>(X, Wq);
    calc_g<<<1, 512>>>(Wq, Wv);
    calc_v<<<16, 256>>>(Wq);
    calc_u<<<512, 256>>>(X);
    attn<<<256, 256, ATTN_SMEM_BYTES>>>(out);
}

// round 6
// speedup vs baseline: 2.9269x; 1.5419x over previous
#include <cuda_runtime.h>
#include <cuda_bf16.h>
#include <cstdint>

#define S_LEN 2048
#define D_DIM 512
#define NH 8
#define NROWS 4096   // B*S
#define NBH 16       // B*H

// ---------------- scratch (static device globals; no allocs) ----------------
__device__ float g_g[D_DIM];
__device__ float g_v[NH * D_DIM];
__device__ float2 g_cu[NBH * S_LEN];                               // {cn, u}
__device__ __align__(128) __nv_bfloat16 g_Qhi[NBH * S_LEN * 64];   // head-major
__device__ __align__(128) __nv_bfloat16 g_Qlo[NBH * S_LEN * 64];
__device__ __align__(128) __nv_bfloat16 g_Xhi[NROWS * D_DIM];      // row-major
__device__ __align__(128) __nv_bfloat16 g_Xlo[NROWS * D_DIM];
__device__ __align__(128) __nv_bfloat16 g_Whi[D_DIM * D_DIM];      // [n][k]
__device__ __align__(128) __nv_bfloat16 g_Wlo[D_DIM * D_DIM];      // [n][k]
__device__ __align__(128) float g_Wt[D_DIM * D_DIM];               // [n][k] fp32

// ---------------- helpers ----------------
__device__ __forceinline__ float ex2(float x) {
    float r; asm("ex2.approx.ftz.f32 %0, %1;" : "=f"(r) : "f"(x)); return r;
}
__device__ __forceinline__ uint32_t smem_u32(const void* p) {
    uint32_t a;
    asm("{ .reg .u64 t; cvta.to.shared.u64 t, %1; cvt.u32.u64 %0, t; }" : "=r"(a) : "l"(p));
    return a;
}
#define LOG2E 1.4426950408889634f
#define SW128(o) ((o) ^ ((((uint32_t)(o)) >> 3) & 0x70))

__device__ __forceinline__ void ldsm4(uint32_t* r, uint32_t addr) {
    asm volatile("ldmatrix.sync.aligned.m8n8.x4.shared.b16 {%0,%1,%2,%3}, [%4];"
                 : "=r"(r[0]), "=r"(r[1]), "=r"(r[2]), "=r"(r[3]) : "r"(addr));
}
__device__ __forceinline__ void mma16816(float* c, const uint32_t* a, const uint32_t* b) {
    asm volatile("mma.sync.aligned.m16n8k16.row.col.f32.bf16.bf16.f32 "
                 "{%0,%1,%2,%3}, {%4,%5,%6,%7}, {%8,%9}, {%0,%1,%2,%3};"
                 : "+f"(c[0]), "+f"(c[1]), "+f"(c[2]), "+f"(c[3])
                 : "r"(a[0]), "r"(a[1]), "r"(a[2]), "r"(a[3]), "r"(b[0]), "r"(b[1]));
}
__device__ __forceinline__ void cp16(uint32_t dst, const void* src) {
    asm volatile("cp.async.cg.shared.global [%0], [%1], 16;" :: "r"(dst), "l"(src));
}
__device__ __forceinline__ void cp_commit() {
    asm volatile("cp.async.commit_group;" ::: "memory");
}
template <int N>
__device__ __forceinline__ void cp_wait() {
    asm volatile("cp.async.wait_group %0;" :: "n"(N) : "memory");
}
__device__ __forceinline__ uint32_t packhl(float a, float b, uint32_t& lo) {
    __nv_bfloat16 h0 = __float2bfloat16(a);
    __nv_bfloat16 h1 = __float2bfloat16(b);
    __nv_bfloat162 hh; hh.x = h0; hh.y = h1;
    __nv_bfloat162 ll;
    ll.x = __float2bfloat16(a - __bfloat162float(h0));
    ll.y = __float2bfloat16(b - __bfloat162float(h1));
    lo = *(uint32_t*)&ll;
    return *(uint32_t*)&hh;
}

// ---------------- convert_w: W[k][n] -> Wt/Whi/Wlo [n][k] ----------------
__global__ __launch_bounds__(256) void convert_w(const float* __restrict__ W) {
    __shared__ float tile[32][33];
    int k0 = (blockIdx.x & 15) * 32;
    int n0 = (blockIdx.x >> 4) * 32;
    int tid = threadIdx.x;
    int r = tid >> 5, c = tid & 31;
#pragma unroll
    for (int p = 0; p < 4; p++)
        tile[p * 8 + r][c] = W[(size_t)(k0 + p * 8 + r) * 512 + n0 + c];
    __syncthreads();
#pragma unroll
    for (int p = 0; p < 4; p++) {
        int nr = p * 8 + r;
        float v = tile[c][nr];           // W[k0+c][n0+nr]
        size_t o = (size_t)(n0 + nr) * 512 + k0 + c;
        g_Wt[o] = v;
        __nv_bfloat16 h = __float2bfloat16(v);
        g_Whi[o] = h;
        g_Wlo[o] = __float2bfloat16(v - __bfloat162float(h));
    }
}

// ---------------- calc_g: g[c] = sum_k W[k][c]*Wv[k] (via Wt rows) --------
__global__ __launch_bounds__(256) void calc_g(const float* __restrict__ Wv) {
    int warp = blockIdx.x * 8 + (threadIdx.x >> 5);   // 512
    int lane = threadIdx.x & 31;
    const float* wt = g_Wt + (size_t)warp * 512;
    float a = 0.f;
#pragma unroll
    for (int m = 0; m < 16; m++) {
        int k = lane + 32 * m;
        a = fmaf(wt[k], Wv[k], a);
    }
#pragma unroll
    for (int o = 16; o > 0; o >>= 1) a += __shfl_xor_sync(0xffffffffu, a, o);
    if (lane == 0) g_g[warp] = a;
}

// ---------------- calc_v: v[h][i] = sum_j Wt[h*64+j][i]*g[h*64+j] ---------
__global__ __launch_bounds__(256) void calc_v() {
    int idx = blockIdx.x * 256 + threadIdx.x;   // 4096
    int h = idx >> 9, i = idx & 511;
    float acc = 0.f;
#pragma unroll
    for (int j = 0; j < 64; j++)
        acc = fmaf(g_Wt[(size_t)(h * 64 + j) * 512 + i], g_g[h * 64 + j], acc);
    g_v[h * 512 + i] = acc;
}

// ---------------- convert_x (+ fused u = X.v) -----------------------------
__global__ __launch_bounds__(256) void convert_x(const float* __restrict__ X) {
    __shared__ float sv[NH * 512];   // 16KB
    int tid = threadIdx.x;
    for (int i = tid; i < NH * 512; i += 256) sv[i] = g_v[i];
    __syncthreads();
    int warp = blockIdx.x * 8 + (tid >> 5);     // 4096 rows
    int lane = tid & 31;
    const float2* xrow = (const float2*)(X + (size_t)warp * 512);
    uint32_t* dhi = (uint32_t*)(g_Xhi + (size_t)warp * 512);
    uint32_t* dlo = (uint32_t*)(g_Xlo + (size_t)warp * 512);
    const float2* sv2 = (const float2*)sv;
    float ua[8];
#pragma unroll
    for (int h = 0; h < 8; h++) ua[h] = 0.f;
#pragma unroll
    for (int m = 0; m < 8; m++) {
        int kp = lane + 32 * m;
        float2 x = xrow[kp];
        uint32_t lo;
        uint32_t hi = packhl(x.x, x.y, lo);
        dhi[kp] = hi;
        dlo[kp] = lo;
#pragma unroll
        for (int h = 0; h < 8; h++) {
            float2 vv = sv2[h * 256 + kp];
            ua[h] = fmaf(x.x, vv.x, ua[h]);
            ua[h] = fmaf(x.y, vv.y, ua[h]);
        }
    }
    int b = warp >> 11, s = warp & 2047;
#pragma unroll
    for (int h = 0; h < 8; h++) {
        float u = ua[h];
#pragma unroll
        for (int o = 16; o > 0; o >>= 1) u += __shfl_xor_sync(0xffffffffu, u, o);
        if (lane == 0) g_cu[(b * 8 + h) * S_LEN + s].y = u;
    }
}

// ---------------- gemm_q (HMMA): Q = X @ W, fused norms + Q hi/lo emit ----
// CTA: 128 rows x 64 cols (one head). K=512 in 8 chunks of 64, double-buffered.
// stage: Ahi 16K | Alo 16K | Bhi 8K | Blo 8K = 48K; x2 = 96K
#define GQ_STAGE 49152
#define GQ_AHI 0
#define GQ_ALO 16384
#define GQ_BHI 32768
#define GQ_BLO 40960
#define GQ_SMEM (2 * GQ_STAGE)

__device__ __forceinline__ void gq_load(uint32_t base,
        const __nv_bfloat16* Ah, const __nv_bfloat16* Al,
        const __nv_bfloat16* Bh, const __nv_bfloat16* Bl,
        int kc, int tid) {
#pragma unroll
    for (int q = 0; q < 4; q++) {
        int idx = q * 256 + tid;           // 0..1023
        int row = idx >> 3, cg = idx & 7;
        uint32_t so = SW128((uint32_t)idx * 16);
        cp16(base + GQ_AHI + so, Ah + (size_t)row * 512 + kc + cg * 8);
        cp16(base + GQ_ALO + so, Al + (size_t)row * 512 + kc + cg * 8);
    }
#pragma unroll
    for (int q = 0; q < 2; q++) {
        int idx = q * 256 + tid;           // 0..511
        int row = idx >> 3, cg = idx & 7;
        uint32_t so = SW128((uint32_t)idx * 16);
        cp16(base + GQ_BHI + so, Bh + (size_t)row * 512 + kc + cg * 8);
        cp16(base + GQ_BLO + so, Bl + (size_t)row * 512 + kc + cg * 8);
    }
}

__global__ __launch_bounds__(256, 2) void gemm_q() {
    extern __shared__ char sm[];
    uint32_t sb = smem_u32(sm);
    int tid = threadIdx.x, lane = tid & 31, w = tid >> 5;
    int bid = blockIdx.x;
    int r0 = (bid >> 3) * 128;
    int h = bid & 7;
    int b = r0 >> 11, srow0 = r0 & 2047;
    const __nv_bfloat16* Ah = g_Xhi + (size_t)r0 * 512;
    const __nv_bfloat16* Al = g_Xlo + (size_t)r0 * 512;
    const __nv_bfloat16* Bh = g_Whi + (size_t)h * 64 * 512;
    const __nv_bfloat16* Bl = g_Wlo + (size_t)h * 64 * 512;

    int row_a = w * 16 + (lane & 15);
    uint32_t a_sw = (uint32_t)((row_a & 7) << 4);
    uint32_t a_hi16 = (uint32_t)((lane >> 4) * 16);
    int nrow_base = (lane & 7) + ((lane >> 4) << 3);
    uint32_t b_sw = (uint32_t)((lane & 7) << 4);
    uint32_t b_c16 = (uint32_t)(((lane >> 3) & 1) * 16);

    float cacc[8][4];
#pragma unroll
    for (int nb = 0; nb < 8; nb++)
#pragma unroll
        for (int r = 0; r < 4; r++) cacc[nb][r] = 0.f;

    gq_load(sb, Ah, Al, Bh, Bl, 0, tid);
    cp_commit();

    for (int i = 0; i < 8; i++) {
        int buf = i & 1;
        __syncthreads();
        if (i < 7) {
            gq_load(sb + (buf ^ 1) * GQ_STAGE, Ah, Al, Bh, Bl, (i + 1) * 64, tid);
            cp_commit();
            cp_wait<1>();
        } else {
            cp_wait<0>();
        }
        __syncthreads();
        uint32_t aHiB = sb + buf * GQ_STAGE + GQ_AHI + (uint32_t)row_a * 128;
        uint32_t aLoB = sb + buf * GQ_STAGE + GQ_ALO + (uint32_t)row_a * 128;
        uint32_t bHiB = sb + buf * GQ_STAGE + GQ_BHI;
        uint32_t bLoB = sb + buf * GQ_STAGE + GQ_BLO;
#pragma unroll
        for (int kk = 0; kk < 4; kk++) {
            uint32_t acol = ((uint32_t)(kk * 32) + a_hi16) ^ a_sw;
            uint32_t ahi[4], alo[4];
            ldsm4(ahi, aHiB + acol);
            ldsm4(alo, aLoB + acol);
            uint32_t bcol = ((uint32_t)(kk * 32) + b_c16) ^ b_sw;
#pragma unroll
            for (int nb2 = 0; nb2 < 4; nb2++) {
                uint32_t boff = (uint32_t)(nrow_base + nb2 * 16) * 128 + bcol;
                uint32_t bhi[4], blo[4];
                ldsm4(bhi, bHiB + boff);
                ldsm4(blo, bLoB + boff);
                mma16816(cacc[2 * nb2],     ahi, bhi);
                mma16816(cacc[2 * nb2],     ahi, blo);
                mma16816(cacc[2 * nb2],     alo, bhi);
                mma16816(cacc[2 * nb2 + 1], ahi, bhi + 2);
                mma16816(cacc[2 * nb2 + 1], ahi, blo + 2);
                mma16816(cacc[2 * nb2 + 1], alo, bhi + 2);
            }
        }
    }
    __syncthreads();   // compute done; smem reusable

    // ---- norms per row (fp32 acc) ----
    float sA = 0.f, sB = 0.f;
#pragma unroll
    for (int nb = 0; nb < 8; nb++) {
        sA = fmaf(cacc[nb][0], cacc[nb][0], sA);
        sA = fmaf(cacc[nb][1], cacc[nb][1], sA);
        sB = fmaf(cacc[nb][2], cacc[nb][2], sB);
        sB = fmaf(cacc[nb][3], cacc[nb][3], sB);
    }
#pragma unroll
    for (int o = 1; o <= 2; o <<= 1) {
        sA += __shfl_xor_sync(0xffffffffu, sA, o);
        sB += __shfl_xor_sync(0xffffffffu, sB, o);
    }
    int rA = w * 16 + (lane >> 2);
    if ((lane & 3) == 0) {
        int base = (b * 8 + h) * S_LEN + srow0;
        g_cu[base + rA].x     = -0.125f * LOG2E * sqrtf(sA);
        g_cu[base + rA + 8].x = -0.125f * LOG2E * sqrtf(sB);
    }

    // ---- stage Q hi/lo (padded [128][33] u32) ----
    uint32_t* sHi32 = (uint32_t*)sm;
    uint32_t* sLo32 = (uint32_t*)(sm + 16896);
#pragma unroll
    for (int nb = 0; nb < 8; nb++) {
        int cslot = nb * 4 + (lane & 3);
        uint32_t lo0, lo1;
        uint32_t hi0 = packhl(cacc[nb][0], cacc[nb][1], lo0);
        uint32_t hi1 = packhl(cacc[nb][2], cacc[nb][3], lo1);
        sHi32[rA * 33 + cslot] = hi0;
        sLo32[rA * 33 + cslot] = lo0;
        sHi32[(rA + 8) * 33 + cslot] = hi1;
        sLo32[(rA + 8) * 33 + cslot] = lo1;
    }
    __syncthreads();
    uint32_t* dH = (uint32_t*)(g_Qhi + ((size_t)(b * 8 + h) * S_LEN + srow0) * 64);
    uint32_t* dL = (uint32_t*)(g_Qlo + ((size_t)(b * 8 + h) * S_LEN + srow0) * 64);
#pragma unroll
    for (int q = 0; q < 16; q++) {              // 16*256 = 4096 u32 = 128 rows x 32
        int linear = q * 256 + tid;
        int row = linear >> 5, c = linear & 31;
        dH[row * 32 + c] = sHi32[row * 33 + c];
        dL[row * 32 + c] = sLo32[row * 33 + c];
    }
}

// ---------------- fused attention (unchanged from R4) ---------------------
#define OFF_QSHI 0
#define OFF_QSLO 16384
#define OFF_QT   32768
#define OFF_CU   98304
#define ATTN_SMEM_BYTES 100352

__global__ __launch_bounds__(256, 2) void attn(float* __restrict__ out) {
    extern __shared__ char sm[];
    uint32_t sb = smem_u32(sm);
    int tid = threadIdx.x;
    int lane = tid & 31, w = tid >> 5;
    int bid = blockIdx.x;
    int stile = bid & 15;
    int bh = bid >> 4;
    int s0 = stile * 128;
    int bhS = bh * S_LEN;

    const __nv_bfloat16* qhiB = g_Qhi + (size_t)bhS * 64;
    const __nv_bfloat16* qloB = g_Qlo + (size_t)bhS * 64;

    {
        const uint4* shi = (const uint4*)(qhiB + (size_t)s0 * 64);
        const uint4* slo = (const uint4*)(qloB + (size_t)s0 * 64);
#pragma unroll
        for (int q = 0; q < 4; q++) {
            uint32_t idx = (uint32_t)(q * 256 + tid);
            uint32_t so = SW128(idx * 16);
            *(uint4*)(sm + OFF_QSHI + so) = shi[idx];
            *(uint4*)(sm + OFF_QSLO + so) = slo[idx];
        }
    }
    {
        const uint4* thi = (const uint4*)qhiB;
        const uint4* tlo = (const uint4*)qloB;
#pragma unroll
        for (int q = 0; q < 4; q++) {
            uint32_t idx = (uint32_t)(q * 256 + tid);
            uint32_t so = SW128(idx * 16);
            cp16(sb + OFF_QT + so, thi + idx);
            cp16(sb + OFF_QT + 16384 + so, tlo + idx);
        }
        if (tid < 64) cp16(sb + OFF_CU + tid * 16, (const char*)(g_cu + bhS) + tid * 16);
        cp_commit();
    }

    int row_a = w * 16 + (lane & 15);
    uint32_t a_sw = (uint32_t)((row_a & 7) << 4);
    uint32_t a_hi16 = (uint32_t)((lane >> 4) * 16);
    uint32_t aBaseHi = sb + OFF_QSHI + (uint32_t)row_a * 128;
    uint32_t aBaseLo = sb + OFF_QSLO + (uint32_t)row_a * 128;
    int nrow_base = (lane & 7) + ((lane >> 4) << 3);
    uint32_t b_sw = (uint32_t)((lane & 7) << 4);
    uint32_t b_c16 = (uint32_t)(((lane >> 3) & 1) * 16);

    const float C1 = 0.25f * LOG2E;
    float den0 = 0.f, num0 = 0.f, den1 = 0.f, num1 = 0.f;

    for (int it = 0; it < 16; it++) {
        int buf = it & 1;
        __syncthreads();
        if (it < 15) {
            int t1 = (it + 1) * 128;
            const uint4* thi = (const uint4*)(qhiB + (size_t)t1 * 64);
            const uint4* tlo = (const uint4*)(qloB + (size_t)t1 * 64);
            uint32_t base = sb + OFF_QT + (buf ^ 1) * 32768;
#pragma unroll
            for (int q = 0; q < 4; q++) {
                uint32_t idx = (uint32_t)(q * 256 + tid);
                uint32_t so = SW128(idx * 16);
                cp16(base + so, thi + idx);
                cp16(base + 16384 + so, tlo + idx);
            }
            if (tid < 64)
                cp16(sb + OFF_CU + (buf ^ 1) * 1024 + tid * 16,
                     (const char*)(g_cu + bhS + t1) + tid * 16);
            cp_commit();
            cp_wait<1>();
        } else {
            cp_wait<0>();
        }
        __syncthreads();

        uint32_t btHi = sb + OFF_QT + buf * 32768;
        uint32_t btLo = btHi + 16384;
        const float2* scu = (const float2*)(sm + OFF_CU + buf * 1024);

        float cacc[16][4];
#pragma unroll
        for (int nb = 0; nb < 16; nb++)
#pragma unroll
            for (int r = 0; r < 4; r++) cacc[nb][r] = 0.f;

#pragma unroll
        for (int kk = 0; kk < 4; kk++) {
            uint32_t acol = ((uint32_t)(kk * 32) + a_hi16) ^ a_sw;
            uint32_t ahi[4], alo[4];
            ldsm4(ahi, aBaseHi + acol);
            ldsm4(alo, aBaseLo + acol);
            uint32_t bcol = ((uint32_t)(kk * 32) + b_c16) ^ b_sw;
#pragma unroll
            for (int nb2 = 0; nb2 < 8; nb2++) {
                uint32_t boff = (uint32_t)(nrow_base + nb2 * 16) * 128 + bcol;
                uint32_t bhi[4], blo[4];
                ldsm4(bhi, btHi + boff);
                ldsm4(blo, btLo + boff);
                mma16816(cacc[2 * nb2],     ahi, bhi);
                mma16816(cacc[2 * nb2],     ahi, blo);
                mma16816(cacc[2 * nb2],     alo, bhi);
                mma16816(cacc[2 * nb2 + 1], ahi, bhi + 2);
                mma16816(cacc[2 * nb2 + 1], ahi, blo + 2);
                mma16816(cacc[2 * nb2 + 1], alo, bhi + 2);
            }
        }

#pragma unroll
        for (int nb = 0; nb < 16; nb++) {
            int col0 = nb * 8 + (lane & 3) * 2;
            float2 cuA = scu[col0];
            float2 cuB = scu[col0 + 1];
            float w0 = ex2(fmaf(cacc[nb][0], C1, cuA.x));
            float w1 = ex2(fmaf(cacc[nb][1], C1, cuB.x));
            float w2 = ex2(fmaf(cacc[nb][2], C1, cuA.x));
            float w3 = ex2(fmaf(cacc[nb][3], C1, cuB.x));
            den0 += w0; num0 = fmaf(w0, cuA.y, num0);
            den0 += w1; num0 = fmaf(w1, cuB.y, num0);
            den1 += w2; num1 = fmaf(w2, cuA.y, num1);
            den1 += w3; num1 = fmaf(w3, cuB.y, num1);
        }
    }

#pragma unroll
    for (int o = 1; o <= 2; o <<= 1) {
        den0 += __shfl_xor_sync(0xffffffffu, den0, o);
        num0 += __shfl_xor_sync(0xffffffffu, num0, o);
        den1 += __shfl_xor_sync(0xffffffffu, den1, o);
        num1 += __shfl_xor_sync(0xffffffffu, num1, o);
    }
    if ((lane & 3) == 0) {
        int gr = lane >> 2;
        int r0 = w * 16 + gr;
        float z0 = num0 / den0;
        float z1 = num1 / den1;
        out[bhS + s0 + r0]     = 1.0f / (1.0f + ex2(-z0 * LOG2E));
        out[bhS + s0 + r0 + 8] = 1.0f / (1.0f + ex2(-z1 * LOG2E));
    }
}

// ---------------- launch ----------------
extern "C" void kernel_launch(void* const* d_in, const int* in_sizes, int n_in,
                              void* d_out, int out_size) {
    const float *X = nullptr, *Wq = nullptr, *Wv = nullptr;
    for (int i = 0; i < n_in; i++) {
        if (in_sizes[i] == 2 * 2048 * 512)      X  = (const float*)d_in[i];
        else if (in_sizes[i] == 512 * 512)      Wq = (const float*)d_in[i];
        else if (in_sizes[i] == 512)            Wv = (const float*)d_in[i];
    }
    float* out = (float*)d_out;

    cudaFuncSetAttribute(gemm_q, cudaFuncAttributeMaxDynamicSharedMemorySize, GQ_SMEM);
    cudaFuncSetAttribute(attn, cudaFuncAttributeMaxDynamicSharedMemorySize, ATTN_SMEM_BYTES);

    convert_w<<<256, 256>>>(Wq);
    calc_g<<<64, 256>>>(Wv);
    calc_v<<<16, 256>>>();
    convert_x<<<512, 256>>>(X);
    gemm_q<<<256, 256, GQ_SMEM>>>();
    attn<<<256, 256, ATTN_SMEM_BYTES>>>(out);
}